// round 12
// baseline (speedup 1.0000x reference)
#include <cuda_runtime.h>
#include <cstdint>

// Problem geometry: velocity (B=2, D=128, H=128, W=128, C=3) float32
#define B_  2
#define DIM 128
#define VOX_PER_B (DIM * DIM * DIM)          // 2097152 = 1<<21
#define N_VOX (B_ * VOX_PER_B)               // 4194304

// Shifted-pair quantized layout: P[i] = (enc(v[i]), enc(v[i_next])), 8 B/voxel,
// i_next = i with x -> (x+1) mod 128. enc = 11/11/10-bit biased fixed point,
// per-step range R_k. One LDG.64 per trilinear row fetches BOTH x-corners.
// Decode/encode use the fp32 mantissa magic 8192 (0x46000000): ulp = 2^-10,
// zero I2F/F2I instructions.
__device__ uint2 g_bufA[N_VOX];
__device__ uint2 g_bufB[N_VOX];

// ---- magic decode: field q at mantissa bits [10:21) of exponent-2^13 float ----
static __device__ __forceinline__ float dec_fz(unsigned W)
{ return __uint_as_float(((W << 10) & 0x001FFC00u) | 0x46000000u); }  // 8192 + qz
static __device__ __forceinline__ float dec_fy(unsigned W)
{ return __uint_as_float(((W >> 1) & 0x001FFC00u) | 0x46000000u); }   // 8192 + qy
static __device__ __forceinline__ float dec_fx(unsigned W)
{ return __uint_as_float(((W >> 12) & 0x000FFC00u) | 0x46000000u); }  // 8192 + qx

// ---- magic encode: q = trunc(v*inv + bias + 0.5), no F2I ----
static __device__ __forceinline__ unsigned enc_v(float vz, float vy, float vx,
                                                 float inv11, float inv10)
{
    float tz = fminf(fmaxf(fmaf(vz, inv11, 9216.5f), 8192.f), 10239.f); // 8192+1024.5
    float ty = fminf(fmaxf(fmaf(vy, inv11, 9216.5f), 8192.f), 10239.f);
    float tx = fminf(fmaxf(fmaf(vx, inv10, 8704.5f), 8192.f), 9215.f);  // 8192+512.5
    unsigned qz = (__float_as_uint(tz) >> 10) & 2047u;
    unsigned qy = (__float_as_uint(ty) >> 10) & 2047u;
    unsigned qx = (__float_as_uint(tx) >> 10) & 1023u;
    return qz | (qy << 11) | (qx << 22);
}

// -------- convert: fp32 float3 AoS -> quantized shifted-pair, fused 1/256 scale ----
__global__ __launch_bounds__(256)
void convert_kernel(const float* __restrict__ in, uint2* __restrict__ out,
                    float s, float inv11, float inv10)
{
    int lane = threadIdx.x & 31;
    int row  = (blockIdx.x * 256 + threadIdx.x) >> 5;   // 0..32767
    int base = row * 128 + lane * 4;

    const float4* in4 = (const float4*)in;
    int fb = row * 96 + lane * 3;
    float4 a = in4[fb + 0];
    float4 b = in4[fb + 1];
    float4 c = in4[fb + 2];

    unsigned e0 = enc_v(a.x * s, a.y * s, a.z * s, inv11, inv10);
    unsigned e1 = enc_v(a.w * s, b.x * s, b.y * s, inv11, inv10);
    unsigned e2 = enc_v(b.z * s, b.w * s, c.x * s, inv11, inv10);
    unsigned e3 = enc_v(c.y * s, c.z * s, c.w * s, inv11, inv10);

    unsigned en = __shfl_sync(0xffffffffu, e0, (lane + 1) & 31);

    out[base + 0] = make_uint2(e0, e1);
    out[base + 1] = make_uint2(e1, e2);
    out[base + 2] = make_uint2(e2, e3);
    out[base + 3] = make_uint2(e3, en);
}

// -------- one squaring step on quantized shifted-pair layout --------
// dec_s11/dec_s10: decode scales of src; off11/off10 = -(8192+bias)*scale.
// enc_inv11/enc_inv10: encode scales of dst.
// LAST=0: dst quantized pairs. LAST=1: dst3 stride-3 fp32 output + identity grid.
template <int LAST>
__global__ __launch_bounds__(256)
void gridexp_step(const uint2* __restrict__ src, uint2* __restrict__ dst,
                  float* __restrict__ dst3,
                  float dec_s11, float dec_s10, float off11, float off10,
                  float enc_inv11, float enc_inv10)
{
    const int idx = blockIdx.x * 256 + threadIdx.x;   // grid sized exactly

    const int b = idx >> 21;
    const int r = idx & (VOX_PER_B - 1);
    const int z = r >> 14;
    const int y = (r >> 7) & 127;
    const int x = r & 127;
    const int base = b << 21;

    // own value: magic decode of the low pair word
    const unsigned W = src[idx].x;
    float vz = fmaf(dec_fz(W), dec_s11, off11);
    float vy = fmaf(dec_fy(W), dec_s11, off11);
    float vx = fmaf(dec_fx(W), dec_s10, off10);

    float phz = (float)z + vz;
    float phy = (float)y + vy;
    float phx = (float)x + vx;

    int iz = __float2int_rd(phz);
    int iy = __float2int_rd(phy);
    int ix = __float2int_rd(phx);
    float wz1 = phz - (float)iz;
    float wy1 = phy - (float)iy;
    float wx1 = phx - (float)ix;
    float wz0 = 1.0f - wz1, wy0 = 1.0f - wy1, wx0 = 1.0f - wx1;

    int z0 = iz & 127, z1 = (iz + 1) & 127;
    int y0 = iy & 127, y1 = (iy + 1) & 127;
    int x0 = ix & 127;                         // x1 handled by pair encoding

    int rows[4];
    rows[0] = base + (z0 << 14) + (y0 << 7) + x0;
    rows[1] = base + (z0 << 14) + (y1 << 7) + x0;
    rows[2] = base + (z1 << 14) + (y0 << 7) + x0;
    rows[3] = base + (z1 << 14) + (y1 << 7) + x0;

    float wzy[4];
    wzy[0] = wz0 * wy0;
    wzy[1] = wz0 * wy1;
    wzy[2] = wz1 * wy0;
    wzy[3] = wz1 * wy1;

    // issue all 4 pair-loads up front for MLP
    uint2 q[4];
#pragma unroll
    for (int rr = 0; rr < 4; ++rr) q[rr] = __ldg(src + rows[rr]);

    // accumulate Σ w * (8192 + q); Σw = 1 folds the magic+bias into one affine
    float az = 0.f, ay = 0.f, ax = 0.f;
#pragma unroll
    for (int rr = 0; rr < 4; ++rr) {
        float u0 = wzy[rr] * wx0;
        float u1 = wzy[rr] * wx1;
        unsigned q0 = q[rr].x, q1 = q[rr].y;
        az = fmaf(u0, dec_fz(q0), az);
        az = fmaf(u1, dec_fz(q1), az);
        ay = fmaf(u0, dec_fy(q0), ay);
        ay = fmaf(u1, dec_fy(q1), ay);
        ax = fmaf(u0, dec_fx(q0), ax);
        ax = fmaf(u1, dec_fx(q1), ax);
    }
    float sz = fmaf(az, dec_s11, off11);
    float sy = fmaf(ay, dec_s11, off11);
    float sx = fmaf(ax, dec_s10, off10);

    float oz = vz + sz;
    float oy = vy + sy;
    float ox = vx + sx;

    if (LAST) {
        float* o = dst3 + (size_t)idx * 3;
        o[0] = oz + (float)z;
        o[1] = oy + (float)y;
        o[2] = ox + (float)x;
    } else {
        // encode and build pair: neighbor (x+1, wrapped) via shuffle + smem handoff
        __shared__ unsigned sb[8];
        const int w = threadIdx.x >> 5;
        const int lane = threadIdx.x & 31;

        unsigned Wn0 = enc_v(oz, oy, ox, enc_inv11, enc_inv10);
        if (lane == 0) sb[w] = Wn0;
        __syncthreads();
        unsigned Wn1 = __shfl_sync(0xffffffffu, Wn0, (lane + 1) & 31);
        if (lane == 31) {
            Wn1 = sb[(w & 4) | ((w + 1) & 3)];   // row wrap within block (2 rows x 4 warps)
        }
        dst[idx] = make_uint2(Wn0, Wn1);
    }
}

extern "C" void kernel_launch(void* const* d_in, const int* in_sizes, int n_in,
                              void* d_out, int out_size)
{
    (void)in_sizes; (void)n_in; (void)out_size;
    const float* vel = (const float*)d_in[0];
    float* out = (float*)d_out;

    uint2* bufA = nullptr;
    uint2* bufB = nullptr;
    cudaGetSymbolAddress((void**)&bufA, g_bufA);
    cudaGetSymbolAddress((void**)&bufB, g_bufB);

    // per-step ranges: R_k = (7/256) * 2^k ; |v_{k+1}| <= 2 R_k = R_{k+1} by construction
    float R[9];
    for (int k = 0; k <= 8; ++k) R[k] = (7.0f / 256.0f) * (float)(1 << k);

    const int threads = 256;

    convert_kernel<<<32768 * 32 / threads, threads>>>(
        vel, bufA, 1.0f / 256.0f, 1024.0f / R[0], 512.0f / R[0]);

    const int blocks = N_VOX / threads;  // 16384
    uint2* cur = bufA;
    uint2* nxt = bufB;
    for (int i = 0; i < 7; ++i) {
        float s11 = R[i] / 1024.0f;
        float s10 = R[i] / 512.0f;
        gridexp_step<0><<<blocks, threads>>>(
            cur, nxt, nullptr,
            s11, s10,
            -(8192.0f + 1024.0f) * s11, -(8192.0f + 512.0f) * s10,
            1024.0f / R[i + 1], 512.0f / R[i + 1]);
        uint2* t = cur; cur = nxt; nxt = t;
    }
    {
        float s11 = R[7] / 1024.0f;
        float s10 = R[7] / 512.0f;
        gridexp_step<1><<<blocks, threads>>>(
            cur, nullptr, out,
            s11, s10,
            -(8192.0f + 1024.0f) * s11, -(8192.0f + 512.0f) * s10,
            0.f, 0.f);
    }
}

// round 13
// speedup vs baseline: 1.1642x; 1.1642x over previous
#include <cuda_runtime.h>
#include <cuda_fp16.h>
#include <cstdint>

// Problem geometry: velocity (B=2, D=128, H=128, W=128, C=3) float32
#define B_  2
#define DIM 128
#define VOX_PER_B (DIM * DIM * DIM)          // 2097152 = 1<<21
#define N_VOX (B_ * VOX_PER_B)               // 4194304
#define ZHALF (64 << 14)

// Ping-pong scratch: 8 B/voxel = (half2(vz,vy), half2(vx,0)) packed in uint2
__device__ uint2 g_bufA[N_VOX];
__device__ uint2 g_bufB[N_VOX];

static __device__ __forceinline__ uint2 pack_v(float vz, float vy, float vx)
{
    __half2 h0 = __floats2half2_rn(vz, vy);
    __half2 h1 = __floats2half2_rn(vx, 0.f);
    uint2 r;
    r.x = *(const unsigned int*)&h0;
    r.y = *(const unsigned int*)&h1;
    return r;
}

// -------- convert: float3 AoS fp32 input -> packed fp16, fused 1/2^STEPS scale --------
__global__ __launch_bounds__(256)
void convert_kernel(const float* __restrict__ in, uint2* __restrict__ out, float s)
{
    int t = blockIdx.x * blockDim.x + threadIdx.x;   // one thread = 4 voxels
    if (t >= N_VOX / 4) return;
    const float4* in4 = (const float4*)in;
    float4 a = in4[t * 3 + 0];
    float4 b = in4[t * 3 + 1];
    float4 c = in4[t * 3 + 2];
    out[t * 4 + 0] = pack_v(a.x * s, a.y * s, a.z * s);
    out[t * 4 + 1] = pack_v(a.w * s, b.x * s, b.y * s);
    out[t * 4 + 2] = pack_v(b.z * s, b.w * s, c.x * s);
    out[t * 4 + 3] = pack_v(c.y * s, c.z * s, c.w * s);
}

// address + weight setup for one voxel
struct Setup {
    int rows[4];
    int x0, x1;
    __half2 wzy2[4];
    __half2 wxlo, wxhi;
    float vz, vy, vx;
};

static __device__ __forceinline__ Setup prep(int base, int z, int y, int x, uint2 pv)
{
    Setup s;
    __half2 pv0 = *(const __half2*)&pv.x;
    __half2 pv1 = *(const __half2*)&pv.y;
    float2 f0 = __half22float2(pv0);
    s.vz = f0.x; s.vy = f0.y;
    s.vx = __low2float(pv1);

    float phz = (float)z + s.vz;
    float phy = (float)y + s.vy;
    float phx = (float)x + s.vx;

    int iz = __float2int_rd(phz);
    int iy = __float2int_rd(phy);
    int ix = __float2int_rd(phx);
    float wz1 = phz - (float)iz;
    float wy1 = phy - (float)iy;
    float wx1 = phx - (float)ix;
    float wz0 = 1.0f - wz1, wy0 = 1.0f - wy1, wx0 = 1.0f - wx1;

    int z0 = iz & 127, z1 = (iz + 1) & 127;
    int y0 = iy & 127, y1 = (iy + 1) & 127;
    s.x0 = ix & 127;
    s.x1 = (ix + 1) & 127;

    s.rows[0] = base + (z0 << 14) + (y0 << 7);
    s.rows[1] = base + (z0 << 14) + (y1 << 7);
    s.rows[2] = base + (z1 << 14) + (y0 << 7);
    s.rows[3] = base + (z1 << 14) + (y1 << 7);

    s.wzy2[0] = __float2half2_rn(wz0 * wy0);
    s.wzy2[1] = __float2half2_rn(wz0 * wy1);
    s.wzy2[2] = __float2half2_rn(wz1 * wy0);
    s.wzy2[3] = __float2half2_rn(wz1 * wy1);
    s.wxlo = __float2half2_rn(wx0);
    s.wxhi = __float2half2_rn(wx1);
    return s;
}

static __device__ __forceinline__ void accum(const Setup& s, const uint2* q,
                                             float& oz, float& oy, float& ox)
{
    const __half2 h2zero = __float2half2_rn(0.f);
    __half2 acc0a = h2zero, acc1a = h2zero;
    __half2 acc0b = h2zero, acc1b = h2zero;
#pragma unroll
    for (int rr = 0; rr < 2; ++rr) {
        __half2 wlo = __hmul2(s.wzy2[rr], s.wxlo);
        __half2 whi = __hmul2(s.wzy2[rr], s.wxhi);
        acc0a = __hfma2(wlo, *(const __half2*)&q[2 * rr].x, acc0a);
        acc1a = __hfma2(wlo, *(const __half2*)&q[2 * rr].y, acc1a);
        acc0a = __hfma2(whi, *(const __half2*)&q[2 * rr + 1].x, acc0a);
        acc1a = __hfma2(whi, *(const __half2*)&q[2 * rr + 1].y, acc1a);
    }
#pragma unroll
    for (int rr = 2; rr < 4; ++rr) {
        __half2 wlo = __hmul2(s.wzy2[rr], s.wxlo);
        __half2 whi = __hmul2(s.wzy2[rr], s.wxhi);
        acc0b = __hfma2(wlo, *(const __half2*)&q[2 * rr].x, acc0b);
        acc1b = __hfma2(wlo, *(const __half2*)&q[2 * rr].y, acc1b);
        acc0b = __hfma2(whi, *(const __half2*)&q[2 * rr + 1].x, acc0b);
        acc1b = __hfma2(whi, *(const __half2*)&q[2 * rr + 1].y, acc1b);
    }
    __half2 acc0 = __hadd2(acc0a, acc0b);
    __half2 acc1 = __hadd2(acc1a, acc1b);

    float2 s0 = __half22float2(acc0);
    oz = s.vz + s0.x;
    oy = s.vy + s0.y;
    ox = s.vx + __low2float(acc1);
}

// -------- one squaring step: 2 z-split voxels/thread, 16-load batch for MLP --------
// LAST=0: dst (packed fp16 scratch). LAST=1: dst3 (stride-3 fp32 output) + identity grid.
template <int LAST>
__global__ __launch_bounds__(256)
void gridexp_step(const uint2* __restrict__ src, uint2* __restrict__ dst,
                  float* __restrict__ dst3)
{
    const int t = blockIdx.x * 256 + threadIdx.x;     // 0 .. N_VOX/2-1
    const int b = t >> 20;
    const int r = t & ((1 << 20) - 1);
    const int z = r >> 14;                            // 0..63
    const int y = (r >> 7) & 127;
    const int x = r & 127;
    const int base = b << 21;
    const int idx0 = base + r;
    const int idx1 = idx0 + ZHALF;

    // both own-loads up front
    uint2 pv0 = __ldg(src + idx0);
    uint2 pv1 = __ldg(src + idx1);

    // both setups (addresses + weights)
    Setup s0 = prep(base, z,      y, x, pv0);
    Setup s1 = prep(base, z + 64, y, x, pv1);

    // one 16-load batch: maximum memory-level parallelism
    uint2 q0[8], q1[8];
#pragma unroll
    for (int rr = 0; rr < 4; ++rr) {
        q0[2 * rr + 0] = __ldg(src + s0.rows[rr] + s0.x0);
        q0[2 * rr + 1] = __ldg(src + s0.rows[rr] + s0.x1);
    }
#pragma unroll
    for (int rr = 0; rr < 4; ++rr) {
        q1[2 * rr + 0] = __ldg(src + s1.rows[rr] + s1.x0);
        q1[2 * rr + 1] = __ldg(src + s1.rows[rr] + s1.x1);
    }

    float oz0, oy0, ox0, oz1, oy1, ox1;
    accum(s0, q0, oz0, oy0, ox0);
    accum(s1, q1, oz1, oy1, ox1);

    if (LAST) {
        float* o0 = dst3 + (size_t)idx0 * 3;
        o0[0] = oz0 + (float)z;
        o0[1] = oy0 + (float)y;
        o0[2] = ox0 + (float)x;
        float* o1 = dst3 + (size_t)idx1 * 3;
        o1[0] = oz1 + (float)(z + 64);
        o1[1] = oy1 + (float)y;
        o1[2] = ox1 + (float)x;
    } else {
        dst[idx0] = pack_v(oz0, oy0, ox0);
        dst[idx1] = pack_v(oz1, oy1, ox1);
    }
}

extern "C" void kernel_launch(void* const* d_in, const int* in_sizes, int n_in,
                              void* d_out, int out_size)
{
    (void)in_sizes; (void)n_in; (void)out_size;
    const float* vel = (const float*)d_in[0];
    float* out = (float*)d_out;

    uint2* bufA = nullptr;
    uint2* bufB = nullptr;
    cudaGetSymbolAddress((void**)&bufA, g_bufA);
    cudaGetSymbolAddress((void**)&bufB, g_bufB);

    const float scale = 1.0f / 256.0f;   // 1 / 2^STEPS, STEPS = 8
    const int threads = 256;

    convert_kernel<<<(N_VOX / 4 + threads - 1) / threads, threads>>>(vel, bufA, scale);

    const int blocks = (N_VOX / 2) / threads;  // exact: 8192
    uint2* cur = bufA;
    uint2* nxt = bufB;
    for (int i = 0; i < 7; ++i) {
        gridexp_step<0><<<blocks, threads>>>(cur, nxt, nullptr);
        uint2* t = cur; cur = nxt; nxt = t;
    }
    gridexp_step<1><<<blocks, threads>>>(cur, nullptr, out);
}